// round 8
// baseline (speedup 1.0000x reference)
#include <cuda_runtime.h>

// Warp-specialized pipeline, 384 threads/CTA, 2 CTAs/SM, one CTA per batch.
//   tid 0-255  (G, 8 warps): P1 (fc1) + P3 (fc2), f32x2 packed FMA.
//   tid 256-351(S, 3 warps): 96 sequential material chains, 4-t batched LDS/STS.
//   tid 352-383:             stages x tiles global->shared (transposed [f][t]).
// buf layout [l][TPAD] (time contiguous). P3 packs f32x2 lanes as (t,t+1):
// y comes packed straight from LDS.128; weights staged DUPLICATED in smem
// (wdup[l][2o]=(w,w)) so the inner loop has zero repack MOVs.

typedef unsigned long long u64;

#define NTHREADS 384
#define TT 32
#define NTILES 32
#define TPAD 36
#define XPAD 36
#define WPADD 36           // duplicated softplus(W2) row stride (floats)
#define XSZ  (16 * XPAD)
#define BSZ  (256 * TPAD)

__device__ __forceinline__ u64 ffma2(u64 a, u64 b, u64 c) {
    u64 d; asm("fma.rn.f32x2 %0, %1, %2, %3;" : "=l"(d) : "l"(a), "l"(b), "l"(c)); return d;
}
__device__ __forceinline__ u64 addf2(u64 a, u64 b) {
    u64 d; asm("add.rn.f32x2 %0, %1, %2;" : "=l"(d) : "l"(a), "l"(b)); return d;
}
__device__ __forceinline__ u64 dup2(float a) {
    u64 r; asm("mov.b64 %0, {%1, %1};" : "=l"(r) : "f"(a)); return r;
}
__device__ __forceinline__ float2 unpack2(u64 v) {
    float2 r; asm("mov.b64 {%0, %1}, %2;" : "=f"(r.x), "=f"(r.y) : "l"(v)); return r;
}

// ---- material constants (reference float32 values) ----
#define NUv    0.3f
#define CEL00  (200.0f / 0.91f)
#define CEL01  (CEL00 * 0.3f)
#define CEL22  (CEL00 * 0.35f)
#define INV_E  (1.0f / 200.0f)
#define INV_G  (2.6f / 200.0f)
#define GMODc  (200.0f / 2.6f)
#define SY0c   2.0f
#define HARDc  10.0f
#define INV3GH (1.0f / (3.0f * GMODc + HARDc))
#define KPEN   50.0f
#define D0c    0.1f
#define INV_DFm (1.0f / 0.9f)

__device__ __forceinline__ void j2_step(float& e1, float& e2, float& e12,
                                        float& ep1, float& ep2, float& ep12, float& epbar)
{
    float d1 = e1 - ep1, d2 = e2 - ep2, d12 = e12 - ep12;
    float s1  = CEL00 * d1 + CEL01 * d2;
    float s2  = CEL01 * d1 + CEL00 * d2;
    float s12 = CEL22 * d12;
    float qv  = fmaxf(s1 * s1 - s1 * s2 + s2 * s2 + 3.0f * s12 * s12, 1e-12f);
    float rs  = rsqrtf(qv);
    float seq = qv * rs;
    float fy  = seq - (SY0c + HARDc * epbar);
    bool  pl  = fy > 0.0f;
    epbar += fmaxf(fy, 0.0f) * INV3GH;
    float r = pl ? (SY0c + HARDc * epbar) * rs : 1.0f;
    s1 *= r; s2 *= r; s12 *= r;
    ep1  = pl ? e1  - (s1 - NUv * s2) * INV_E : ep1;
    ep2  = pl ? e2  - (s2 - NUv * s1) * INV_E : ep2;
    ep12 = pl ? e12 - s12 * INV_G             : ep12;
    e1 = s1; e2 = s2; e12 = s12;
}

__device__ __forceinline__ void coh_step(float& dn, float& ds, float& hist)
{
    float dnp = fmaxf(dn, 0.0f);
    float q2  = fmaxf(dnp * dnp + ds * ds, 1e-12f);
    float lam = q2 * rsqrtf(q2);
    hist = fmaxf(hist, lam);
    float dmg = __fdividef(hist - D0c, hist) * INV_DFm;
    dmg = fminf(fmaxf(dmg, 0.0f), 1.0f);
    float omd = 1.0f - dmg;
    float tn = KPEN * dn * (dn > 0.0f ? omd : 1.0f);
    ds = omd * KPEN * ds;
    dn = tn;
}

__global__ void __launch_bounds__(NTHREADS, 2)
fused_fea_kernel(const float* __restrict__ x, const float* __restrict__ W1,
                 const float* __restrict__ W2, float* __restrict__ out)
{
    extern __shared__ float sm[];
    float* wdup = sm;                    // 256*WPADD, softplus(W2) lane-duplicated
    float* xsd  = sm + 256 * WPADD;      // 2 * XSZ, x transposed [f][t]
    float* buf  = xsd + 2 * XSZ;         // 2 * BSZ, [l][t]

    const int tid = threadIdx.x;
    const int b   = blockIdx.x;
    const bool isG = (tid < 256);

    const float* xb = x   + (size_t)b * (1024 * 16);
    float*       ob = out + (size_t)b * (1024 * 16);

    // ---- Prologue: duplicated softplus(W2); stager fills x tiles 0,1 ----
    for (int i = tid; i < 4096; i += NTHREADS) {
        int o = i >> 8, l = i & 255;
        float v = log1pf(expf(W2[i]));
        *(u64*)(wdup + l * WPADD + 2 * o) = dup2(v);
    }
    if (tid >= 352) {
        const int j = tid - 352;
#pragma unroll
        for (int tile = 0; tile < 2; ++tile) {
            const float4* src = (const float4*)(xb + tile * (TT * 16) + j * 16);
            float* dst = xsd + tile * XSZ + j;
            float4 v0 = src[0], v1 = src[1], v2 = src[2], v3 = src[3];
            dst[0*XPAD] = v0.x; dst[1*XPAD]  = v0.y; dst[2*XPAD]  = v0.z; dst[3*XPAD]  = v0.w;
            dst[4*XPAD] = v1.x; dst[5*XPAD]  = v1.y; dst[6*XPAD]  = v1.z; dst[7*XPAD]  = v1.w;
            dst[8*XPAD] = v2.x; dst[9*XPAD]  = v2.y; dst[10*XPAD] = v2.z; dst[11*XPAD] = v2.w;
            dst[12*XPAD]= v3.x; dst[13*XPAD] = v3.y; dst[14*XPAD] = v3.z; dst[15*XPAD] = v3.w;
        }
    }

    // G/P1: one channel per thread, duplicated weights in regs.
    // Cohesive channels l>=192 stored comp-planar: row = 192+((l-192)>>1)+32*(l&1).
    u64 wd[16];
    int rowp = 0;
    if (isG) {
        const int c = tid;
        rowp = (c < 192) ? c : 192 + ((c - 192) >> 1) + 32 * (c & 1);
#pragma unroll
        for (int f = 0; f < 16; ++f) wd[f] = dup2(W1[c * 16 + f]);
    }

    // S state
    float ep1 = 0.f, ep2 = 0.f, ep12 = 0.f, epbar = 0.f, hist = 0.f;
    const int s = tid - 256;

    // P3 coords: lc = l-strip (l = 8i+lc), oq = output quad, tq = 4-t group.
    const int lc = tid & 7;
    const int oq = (tid >> 3) & 3;
    const int tq = tid >> 5;             // 0..7 for G threads
    const int rowc_base = 192 + (lc >> 1) + 32 * (lc & 1);

    __syncthreads();

    // ================= P1 (one tile) =================
#define P1_TILE(BSEL, XSEL)                                                   \
    {                                                                         \
        float* bufb = buf + (BSEL) * BSZ;                                     \
        const float* xsb = xsd + (XSEL) * XSZ;                                \
        _Pragma("unroll")                                                     \
        for (int g = 0; g < 8; ++g) {                                         \
            const int t = g * 4;                                              \
            u64 a0 = 0, a1 = 0;                                               \
            _Pragma("unroll")                                                 \
            for (int f = 0; f < 16; ++f) {                                    \
                ulonglong2 xv = *(const ulonglong2*)(xsb + f * XPAD + t);     \
                a0 = ffma2(wd[f], xv.x, a0);                                  \
                a1 = ffma2(wd[f], xv.y, a1);                                  \
            }                                                                 \
            ulonglong2 sv; sv.x = a0; sv.y = a1;                              \
            *(ulonglong2*)(bufb + rowp * TPAD + t) = sv;                      \
        }                                                                     \
    }

    // ================= P3 (one tile) =================
    // acc[2*o + tp] accumulates outputs (4oq+o) for packed times (4tq+2tp, +1).
#define P3_TILE(BSEL, TOUT)                                                   \
    {                                                                         \
        const float* bufb = buf + (BSEL) * BSZ;                               \
        u64 acc[8];                                                           \
        _Pragma("unroll")                                                     \
        for (int m = 0; m < 8; ++m) acc[m] = 0ull;                            \
        const float* ybulk = bufb + lc * TPAD + 4 * tq;                       \
        const float* wrow  = wdup + lc * WPADD + 8 * oq;                      \
        _Pragma("unroll 4")                                                   \
        for (int i = 0; i < 24; ++i) {                                        \
            ulonglong2 yv = *(const ulonglong2*)(ybulk + i * 8 * TPAD);       \
            ulonglong2 w01 = *(const ulonglong2*)(wrow + i * 8 * WPADD);      \
            ulonglong2 w23 = *(const ulonglong2*)(wrow + i * 8 * WPADD + 4);  \
            acc[0] = ffma2(w01.x, yv.x, acc[0]); acc[1] = ffma2(w01.x, yv.y, acc[1]); \
            acc[2] = ffma2(w01.y, yv.x, acc[2]); acc[3] = ffma2(w01.y, yv.y, acc[3]); \
            acc[4] = ffma2(w23.x, yv.x, acc[4]); acc[5] = ffma2(w23.x, yv.y, acc[5]); \
            acc[6] = ffma2(w23.y, yv.x, acc[6]); acc[7] = ffma2(w23.y, yv.y, acc[7]); \
        }                                                                     \
        const float* ycoh = bufb + rowc_base * TPAD + 4 * tq;                 \
        _Pragma("unroll 4")                                                   \
        for (int i = 24; i < 32; ++i) {                                       \
            ulonglong2 yv = *(const ulonglong2*)(ycoh + (i - 24) * 4 * TPAD); \
            ulonglong2 w01 = *(const ulonglong2*)(wrow + i * 8 * WPADD);      \
            ulonglong2 w23 = *(const ulonglong2*)(wrow + i * 8 * WPADD + 4);  \
            acc[0] = ffma2(w01.x, yv.x, acc[0]); acc[1] = ffma2(w01.x, yv.y, acc[1]); \
            acc[2] = ffma2(w01.y, yv.x, acc[2]); acc[3] = ffma2(w01.y, yv.y, acc[3]); \
            acc[4] = ffma2(w23.x, yv.x, acc[4]); acc[5] = ffma2(w23.x, yv.y, acc[5]); \
            acc[6] = ffma2(w23.y, yv.x, acc[6]); acc[7] = ffma2(w23.y, yv.y, acc[7]); \
        }                                                                     \
        _Pragma("unroll")                                                     \
        for (int m = 0; m < 8; ++m) {                                         \
            acc[m] = addf2(acc[m], __shfl_xor_sync(0xffffffffu, acc[m], 1));  \
            acc[m] = addf2(acc[m], __shfl_xor_sync(0xffffffffu, acc[m], 2));  \
            acc[m] = addf2(acc[m], __shfl_xor_sync(0xffffffffu, acc[m], 4));  \
        }                                                                     \
        if (lc == 0) {                                                        \
            float* og = ob + (size_t)((TOUT) + 4 * tq) * 16 + 4 * oq;         \
            float2 p0 = unpack2(acc[0]), p2 = unpack2(acc[2]);                \
            float2 p4 = unpack2(acc[4]), p6 = unpack2(acc[6]);                \
            float2 q0 = unpack2(acc[1]), q2 = unpack2(acc[3]);                \
            float2 q4 = unpack2(acc[5]), q6 = unpack2(acc[7]);                \
            float4 v;                                                         \
            v.x = p0.x; v.y = p2.x; v.z = p4.x; v.w = p6.x;                   \
            *(float4*)(og)      = v;                                          \
            v.x = p0.y; v.y = p2.y; v.z = p4.y; v.w = p6.y;                   \
            *(float4*)(og + 16) = v;                                          \
            v.x = q0.x; v.y = q2.x; v.z = q4.x; v.w = q6.x;                   \
            *(float4*)(og + 32) = v;                                          \
            v.x = q0.y; v.y = q2.y; v.z = q4.y; v.w = q6.y;                   \
            *(float4*)(og + 48) = v;                                          \
        }                                                                     \
    }

    // ---- Fill: P1(0) ----
    if (isG) P1_TILE(0, 0);
    __syncthreads();

    // ---- Pipelined slots ----
    for (int k = 0; k < NTILES; ++k) {
        if (isG) {
            if (k >= 1) P3_TILE((k - 1) & 1, (k - 1) * TT);
            asm volatile("bar.sync 1, 256;" ::: "memory");
            if (k + 1 < NTILES) P1_TILE((k + 1) & 1, (k + 1) & 1);
        } else if (s < 64) {
            // J2 bulk: rows 3s..3s+2; 4 timesteps per LDS/STS.128.
            float* r0 = buf + (k & 1) * BSZ + (3 * s) * TPAD;
#pragma unroll
            for (int g = 0; g < 8; ++g) {
                float4 E1 = *(float4*)(r0 + 4 * g);
                float4 E2 = *(float4*)(r0 + TPAD + 4 * g);
                float4 E3 = *(float4*)(r0 + 2 * TPAD + 4 * g);
                j2_step(E1.x, E2.x, E3.x, ep1, ep2, ep12, epbar);
                j2_step(E1.y, E2.y, E3.y, ep1, ep2, ep12, epbar);
                j2_step(E1.z, E2.z, E3.z, ep1, ep2, ep12, epbar);
                j2_step(E1.w, E2.w, E3.w, ep1, ep2, ep12, epbar);
                *(float4*)(r0 + 4 * g) = E1;
                *(float4*)(r0 + TPAD + 4 * g) = E2;
                *(float4*)(r0 + 2 * TPAD + 4 * g) = E3;
            }
        } else if (s < 96) {
            // Cohesive: dn row 192+j, ds row 224+j.
            const int j = s - 64;
            float* rdn = buf + (k & 1) * BSZ + (192 + j) * TPAD;
            float* rds = buf + (k & 1) * BSZ + (224 + j) * TPAD;
#pragma unroll
            for (int g = 0; g < 8; ++g) {
                float4 DN = *(float4*)(rdn + 4 * g);
                float4 DS = *(float4*)(rds + 4 * g);
                coh_step(DN.x, DS.x, hist);
                coh_step(DN.y, DS.y, hist);
                coh_step(DN.z, DS.z, hist);
                coh_step(DN.w, DS.w, hist);
                *(float4*)(rdn + 4 * g) = DN;
                *(float4*)(rds + 4 * g) = DS;
            }
        } else {
            // Stager: x tile (k+2) -> xsd[k&1], transposed [f][t].
            if (k + 2 < NTILES) {
                const int j = tid - 352;
                const float4* src = (const float4*)(xb + (k + 2) * (TT * 16) + j * 16);
                float* dst = xsd + (k & 1) * XSZ + j;
                float4 v0 = src[0], v1 = src[1], v2 = src[2], v3 = src[3];
                dst[0*XPAD] = v0.x; dst[1*XPAD]  = v0.y; dst[2*XPAD]  = v0.z; dst[3*XPAD]  = v0.w;
                dst[4*XPAD] = v1.x; dst[5*XPAD]  = v1.y; dst[6*XPAD]  = v1.z; dst[7*XPAD]  = v1.w;
                dst[8*XPAD] = v2.x; dst[9*XPAD]  = v2.y; dst[10*XPAD] = v2.z; dst[11*XPAD] = v2.w;
                dst[12*XPAD]= v3.x; dst[13*XPAD] = v3.y; dst[14*XPAD] = v3.z; dst[15*XPAD] = v3.w;
            }
        }
        __syncthreads();
    }

    // ---- Drain: P3(NTILES-1) ----
    if (isG) P3_TILE((NTILES - 1) & 1, (NTILES - 1) * TT);
}

extern "C" void kernel_launch(void* const* d_in, const int* in_sizes, int n_in,
                              void* d_out, int out_size)
{
    const float* x  = (const float*)d_in[0];
    const float* W1 = (const float*)d_in[1];
    const float* W2 = (const float*)d_in[2];
    float* out = (float*)d_out;

    const size_t smem = (size_t)(256 * WPADD + 2 * XSZ + 2 * BSZ) * sizeof(float); // 115200 B
    cudaFuncSetAttribute(fused_fea_kernel, cudaFuncAttributeMaxDynamicSharedMemorySize, (int)smem);
    fused_fea_kernel<<<256, NTHREADS, smem>>>(x, W1, W2, out);
}

// round 9
// speedup vs baseline: 1.1506x; 1.1506x over previous
#include <cuda_runtime.h>

// Warp-specialized two-phase pipeline, 384 threads/CTA, 2 CTAs/SM.
//   tid 0-255  (G, 8 warps): phase A: P3 (fc2); phase B: P1 (fc1) for t 0..23.
//   tid 256-351(S, 3 warps): phase A: 96 material chains; phase B: P1 t 24..31.
//   tid 352-383 (stager):    phase A: stage x tile; phase B: P1 t 24..31.
// buf layout [l][TPAD] (time contiguous). P3 = R7 structure (y broadcast 1wf,
// w 4wf, o-packed accs via dup MOVs — the known-best MIO shape).

typedef unsigned long long u64;

#define NTHREADS 384
#define TT 32
#define NTILES 32
#define TPAD 36
#define XPAD 36
#define WPAD 20
#define XSZ  (16 * XPAD)
#define BSZ  (256 * TPAD)

__device__ __forceinline__ u64 ffma2(u64 a, u64 b, u64 c) {
    u64 d; asm("fma.rn.f32x2 %0, %1, %2, %3;" : "=l"(d) : "l"(a), "l"(b), "l"(c)); return d;
}
__device__ __forceinline__ u64 addf2(u64 a, u64 b) {
    u64 d; asm("add.rn.f32x2 %0, %1, %2;" : "=l"(d) : "l"(a), "l"(b)); return d;
}
__device__ __forceinline__ u64 pack2(float a, float b) {
    u64 r; asm("mov.b64 %0, {%1, %2};" : "=l"(r) : "f"(a), "f"(b)); return r;
}
__device__ __forceinline__ u64 dup2(float a) {
    u64 r; asm("mov.b64 %0, {%1, %1};" : "=l"(r) : "f"(a)); return r;
}
__device__ __forceinline__ float2 unpack2(u64 v) {
    float2 r; asm("mov.b64 {%0, %1}, %2;" : "=f"(r.x), "=f"(r.y) : "l"(v)); return r;
}

// ---- material constants (reference float32 values) ----
#define NUv    0.3f
#define CEL00  (200.0f / 0.91f)
#define CEL01  (CEL00 * 0.3f)
#define CEL22  (CEL00 * 0.35f)
#define INV_E  (1.0f / 200.0f)
#define INV_G  (2.6f / 200.0f)
#define GMODc  (200.0f / 2.6f)
#define SY0c   2.0f
#define HARDc  10.0f
#define INV3GH (1.0f / (3.0f * GMODc + HARDc))
#define KPEN   50.0f
#define D0c    0.1f
#define INV_DFm (1.0f / 0.9f)

__device__ __forceinline__ void j2_step(float& e1, float& e2, float& e12,
                                        float& ep1, float& ep2, float& ep12, float& epbar)
{
    float d1 = e1 - ep1, d2 = e2 - ep2, d12 = e12 - ep12;
    float s1  = CEL00 * d1 + CEL01 * d2;
    float s2  = CEL01 * d1 + CEL00 * d2;
    float s12 = CEL22 * d12;
    float qv  = fmaxf(s1 * s1 - s1 * s2 + s2 * s2 + 3.0f * s12 * s12, 1e-12f);
    float rs  = rsqrtf(qv);
    float seq = qv * rs;
    float fy  = seq - (SY0c + HARDc * epbar);
    bool  pl  = fy > 0.0f;
    epbar += fmaxf(fy, 0.0f) * INV3GH;
    float r = pl ? (SY0c + HARDc * epbar) * rs : 1.0f;
    s1 *= r; s2 *= r; s12 *= r;
    ep1  = pl ? e1  - (s1 - NUv * s2) * INV_E : ep1;
    ep2  = pl ? e2  - (s2 - NUv * s1) * INV_E : ep2;
    ep12 = pl ? e12 - s12 * INV_G             : ep12;
    e1 = s1; e2 = s2; e12 = s12;
}

__device__ __forceinline__ void coh_step(float& dn, float& ds, float& hist)
{
    float dnp = fmaxf(dn, 0.0f);
    float q2  = fmaxf(dnp * dnp + ds * ds, 1e-12f);
    float lam = q2 * rsqrtf(q2);
    hist = fmaxf(hist, lam);
    float dmg = __fdividef(hist - D0c, hist) * INV_DFm;
    dmg = fminf(fmaxf(dmg, 0.0f), 1.0f);
    float omd = 1.0f - dmg;
    float tn = KPEN * dn * (dn > 0.0f ? omd : 1.0f);
    ds = omd * KPEN * ds;
    dn = tn;
}

// channel -> buf row (cohesive channels stored comp-planar)
__device__ __forceinline__ int row_of(int c) {
    return (c < 192) ? c : 192 + ((c - 192) >> 1) + 32 * (c & 1);
}

__global__ void __launch_bounds__(NTHREADS, 2)
fused_fea_kernel(const float* __restrict__ x, const float* __restrict__ W1,
                 const float* __restrict__ W2, float* __restrict__ out)
{
    extern __shared__ float sm[];
    float* SW2s = sm;                    // 256*WPAD, softplus(W2) [l][o]
    float* xsd  = sm + 256 * WPAD;       // 2 * XSZ, x transposed [f][t]
    float* buf  = xsd + 2 * XSZ;         // 2 * BSZ, [l][t]

    const int tid = threadIdx.x;
    const int b   = blockIdx.x;
    const bool isG = (tid < 256);

    const float* xb = x   + (size_t)b * (1024 * 16);
    float*       ob = out + (size_t)b * (1024 * 16);

    // ---- Prologue ----
    for (int i = tid; i < 4096; i += NTHREADS) {
        int o = i >> 8, l = i & 255;
        SW2s[l * WPAD + o] = log1pf(expf(W2[i]));
    }
    if (tid >= 352) {
        const int j = tid - 352;
#pragma unroll
        for (int tile = 0; tile < 2; ++tile) {
            const float4* src = (const float4*)(xb + tile * (TT * 16) + j * 16);
            float* dst = xsd + tile * XSZ + j;
            float4 v0 = src[0], v1 = src[1], v2 = src[2], v3 = src[3];
            dst[0*XPAD] = v0.x; dst[1*XPAD]  = v0.y; dst[2*XPAD]  = v0.z; dst[3*XPAD]  = v0.w;
            dst[4*XPAD] = v1.x; dst[5*XPAD]  = v1.y; dst[6*XPAD]  = v1.z; dst[7*XPAD]  = v1.w;
            dst[8*XPAD] = v2.x; dst[9*XPAD]  = v2.y; dst[10*XPAD] = v2.z; dst[11*XPAD] = v2.w;
            dst[12*XPAD]= v3.x; dst[13*XPAD] = v3.y; dst[14*XPAD] = v3.z; dst[15*XPAD] = v3.w;
        }
    }

    // Weight setup.
    // G: one channel (c = tid), lane-duplicated weights (t-packed accs).
    // S-side (tid>=256): packed channel pair (c0 = sid, c1 = sid+128),
    //                    non-dup packed weights (o-packed accs over the pair).
    u64 wreg[16];
    int row0 = 0, row1 = 0;
    if (isG) {
        row0 = row_of(tid);
#pragma unroll
        for (int f = 0; f < 16; ++f) wreg[f] = dup2(W1[tid * 16 + f]);
    } else {
        const int sid = tid - 256;       // 0..127
        row0 = row_of(sid);
        row1 = row_of(sid + 128);
#pragma unroll
        for (int f = 0; f < 16; ++f)
            wreg[f] = pack2(W1[sid * 16 + f], W1[(sid + 128) * 16 + f]);
    }

    // S chain state
    float ep1 = 0.f, ep2 = 0.f, ep12 = 0.f, epbar = 0.f, hist = 0.f;
    const int s = tid - 256;

    // P3 coords (G): lc = l-strip (l = 8i+lc), oq = output quad, tb = 4-t group.
    const int lc = tid & 7;
    const int oq = (tid >> 3) & 3;
    const int tb = tid >> 5;
    const int rowc_base = 192 + (lc >> 1) + 32 * (lc & 1);

    __syncthreads();

    // ===== P1, G side: channel tid, t = 0..23 (6 groups of 4), t-packed =====
#define P1_G(BSEL, XSEL)                                                      \
    {                                                                         \
        float* bufb = buf + (BSEL) * BSZ;                                     \
        const float* xsb = xsd + (XSEL) * XSZ;                                \
        _Pragma("unroll")                                                     \
        for (int g = 0; g < 6; ++g) {                                         \
            const int t = g * 4;                                              \
            u64 a0 = 0, a1 = 0;                                               \
            _Pragma("unroll")                                                 \
            for (int f = 0; f < 16; ++f) {                                    \
                ulonglong2 xv = *(const ulonglong2*)(xsb + f * XPAD + t);     \
                a0 = ffma2(wreg[f], xv.x, a0);                                \
                a1 = ffma2(wreg[f], xv.y, a1);                                \
            }                                                                 \
            ulonglong2 sv; sv.x = a0; sv.y = a1;                              \
            *(ulonglong2*)(bufb + row0 * TPAD + t) = sv;                      \
        }                                                                     \
    }

    // ===== P1, S side: channel pair (sid, sid+128), t = 24..31, o-packed =====
#define P1_S(BSEL, XSEL)                                                      \
    {                                                                         \
        float* bufb = buf + (BSEL) * BSZ;                                     \
        const float* xsb = xsd + (XSEL) * XSZ;                                \
        _Pragma("unroll")                                                     \
        for (int g = 6; g < 8; ++g) {                                         \
            const int t = g * 4;                                              \
            u64 a0 = 0, a1 = 0, a2 = 0, a3 = 0;                               \
            _Pragma("unroll")                                                 \
            for (int f = 0; f < 16; ++f) {                                    \
                float4 xq = *(const float4*)(xsb + f * XPAD + t);             \
                a0 = ffma2(wreg[f], dup2(xq.x), a0);                          \
                a1 = ffma2(wreg[f], dup2(xq.y), a1);                          \
                a2 = ffma2(wreg[f], dup2(xq.z), a2);                          \
                a3 = ffma2(wreg[f], dup2(xq.w), a3);                          \
            }                                                                 \
            float2 h0 = unpack2(a0), h1 = unpack2(a1);                        \
            float2 h2 = unpack2(a2), h3 = unpack2(a3);                        \
            float* r0 = bufb + row0 * TPAD + t;                               \
            float* r1 = bufb + row1 * TPAD + t;                               \
            r0[0] = h0.x; r0[1] = h1.x; r0[2] = h2.x; r0[3] = h3.x;           \
            r1[0] = h0.y; r1[1] = h1.y; r1[2] = h2.y; r1[3] = h3.y;           \
        }                                                                     \
    }

    // ===== P3 (R7 structure) =====
#define P3_TILE(BSEL, TOUT)                                                   \
    {                                                                         \
        const float* bufb = buf + (BSEL) * BSZ;                               \
        u64 acc[8];                                                           \
        _Pragma("unroll")                                                     \
        for (int m = 0; m < 8; ++m) acc[m] = 0ull;                            \
        const float* ybulk = bufb + lc * TPAD + 4 * tb;                       \
        const float* wrow  = SW2s + lc * WPAD + 4 * oq;                       \
        _Pragma("unroll 4")                                                   \
        for (int i = 0; i < 24; ++i) {                                        \
            ulonglong2 yv = *(const ulonglong2*)(ybulk + i * 8 * TPAD);       \
            ulonglong2 wv = *(const ulonglong2*)(wrow + i * 8 * WPAD);        \
            float2 y01 = unpack2(yv.x), y23 = unpack2(yv.y);                  \
            u64 y0 = dup2(y01.x), y1 = dup2(y01.y);                           \
            u64 y2 = dup2(y23.x), y3 = dup2(y23.y);                           \
            acc[0] = ffma2(wv.x, y0, acc[0]); acc[1] = ffma2(wv.y, y0, acc[1]); \
            acc[2] = ffma2(wv.x, y1, acc[2]); acc[3] = ffma2(wv.y, y1, acc[3]); \
            acc[4] = ffma2(wv.x, y2, acc[4]); acc[5] = ffma2(wv.y, y2, acc[5]); \
            acc[6] = ffma2(wv.x, y3, acc[6]); acc[7] = ffma2(wv.y, y3, acc[7]); \
        }                                                                     \
        const float* ycoh = bufb + rowc_base * TPAD + 4 * tb;                 \
        _Pragma("unroll 4")                                                   \
        for (int i = 24; i < 32; ++i) {                                       \
            ulonglong2 yv = *(const ulonglong2*)(ycoh + (i - 24) * 4 * TPAD); \
            ulonglong2 wv = *(const ulonglong2*)(wrow + i * 8 * WPAD);        \
            float2 y01 = unpack2(yv.x), y23 = unpack2(yv.y);                  \
            u64 y0 = dup2(y01.x), y1 = dup2(y01.y);                           \
            u64 y2 = dup2(y23.x), y3 = dup2(y23.y);                           \
            acc[0] = ffma2(wv.x, y0, acc[0]); acc[1] = ffma2(wv.y, y0, acc[1]); \
            acc[2] = ffma2(wv.x, y1, acc[2]); acc[3] = ffma2(wv.y, y1, acc[3]); \
            acc[4] = ffma2(wv.x, y2, acc[4]); acc[5] = ffma2(wv.y, y2, acc[5]); \
            acc[6] = ffma2(wv.x, y3, acc[6]); acc[7] = ffma2(wv.y, y3, acc[7]); \
        }                                                                     \
        _Pragma("unroll")                                                     \
        for (int m = 0; m < 8; ++m) {                                         \
            acc[m] = addf2(acc[m], __shfl_xor_sync(0xffffffffu, acc[m], 1));  \
            acc[m] = addf2(acc[m], __shfl_xor_sync(0xffffffffu, acc[m], 2));  \
            acc[m] = addf2(acc[m], __shfl_xor_sync(0xffffffffu, acc[m], 4));  \
        }                                                                     \
        if (lc == 0) {                                                        \
            float* og = ob + (size_t)((TOUT) + 4 * tb) * 16 + 4 * oq;         \
            _Pragma("unroll")                                                 \
            for (int j = 0; j < 4; ++j) {                                     \
                float2 p0 = unpack2(acc[2 * j]);                              \
                float2 p1 = unpack2(acc[2 * j + 1]);                          \
                float4 v; v.x = p0.x; v.y = p0.y; v.z = p1.x; v.w = p1.y;     \
                *(float4*)(og + j * 16) = v;                                  \
            }                                                                 \
        }                                                                     \
    }

    // ---- Fill: P1(0) by everyone ----
    if (isG) P1_G(0, 0) else P1_S(0, 0);
    __syncthreads();

    // ---- Pipelined slots: phase A (P3 | P2 | stage), sync, phase B (P1) ----
    for (int k = 0; k < NTILES; ++k) {
        // Phase A
        if (isG) {
            if (k >= 1) P3_TILE((k - 1) & 1, (k - 1) * TT);
        } else if (s < 64) {
            float* r0 = buf + (k & 1) * BSZ + (3 * s) * TPAD;
#pragma unroll
            for (int g = 0; g < 8; ++g) {
                float4 E1 = *(float4*)(r0 + 4 * g);
                float4 E2 = *(float4*)(r0 + TPAD + 4 * g);
                float4 E3 = *(float4*)(r0 + 2 * TPAD + 4 * g);
                j2_step(E1.x, E2.x, E3.x, ep1, ep2, ep12, epbar);
                j2_step(E1.y, E2.y, E3.y, ep1, ep2, ep12, epbar);
                j2_step(E1.z, E2.z, E3.z, ep1, ep2, ep12, epbar);
                j2_step(E1.w, E2.w, E3.w, ep1, ep2, ep12, epbar);
                *(float4*)(r0 + 4 * g) = E1;
                *(float4*)(r0 + TPAD + 4 * g) = E2;
                *(float4*)(r0 + 2 * TPAD + 4 * g) = E3;
            }
        } else if (s < 96) {
            const int j = s - 64;
            float* rdn = buf + (k & 1) * BSZ + (192 + j) * TPAD;
            float* rds = buf + (k & 1) * BSZ + (224 + j) * TPAD;
#pragma unroll
            for (int g = 0; g < 8; ++g) {
                float4 DN = *(float4*)(rdn + 4 * g);
                float4 DS = *(float4*)(rds + 4 * g);
                coh_step(DN.x, DS.x, hist);
                coh_step(DN.y, DS.y, hist);
                coh_step(DN.z, DS.z, hist);
                coh_step(DN.w, DS.w, hist);
                *(float4*)(rdn + 4 * g) = DN;
                *(float4*)(rds + 4 * g) = DS;
            }
        } else {
            if (k + 2 < NTILES) {
                const int j = tid - 352;
                const float4* src = (const float4*)(xb + (k + 2) * (TT * 16) + j * 16);
                float* dst = xsd + (k & 1) * XSZ + j;
                float4 v0 = src[0], v1 = src[1], v2 = src[2], v3 = src[3];
                dst[0*XPAD] = v0.x; dst[1*XPAD]  = v0.y; dst[2*XPAD]  = v0.z; dst[3*XPAD]  = v0.w;
                dst[4*XPAD] = v1.x; dst[5*XPAD]  = v1.y; dst[6*XPAD]  = v1.z; dst[7*XPAD]  = v1.w;
                dst[8*XPAD] = v2.x; dst[9*XPAD]  = v2.y; dst[10*XPAD] = v2.z; dst[11*XPAD] = v2.w;
                dst[12*XPAD]= v3.x; dst[13*XPAD] = v3.y; dst[14*XPAD] = v3.z; dst[15*XPAD] = v3.w;
            }
        }
        __syncthreads();

        // Phase B: P1(k+1) by everyone
        if (k + 1 < NTILES) {
            if (isG) P1_G((k + 1) & 1, (k + 1) & 1)
            else     P1_S((k + 1) & 1, (k + 1) & 1);
        }
        __syncthreads();
    }

    // ---- Drain: P3(NTILES-1) ----
    if (isG) P3_TILE((NTILES - 1) & 1, (NTILES - 1) * TT);
}

extern "C" void kernel_launch(void* const* d_in, const int* in_sizes, int n_in,
                              void* d_out, int out_size)
{
    const float* x  = (const float*)d_in[0];
    const float* W1 = (const float*)d_in[1];
    const float* W2 = (const float*)d_in[2];
    float* out = (float*)d_out;

    const size_t smem = (size_t)(256 * WPAD + 2 * XSZ + 2 * BSZ) * sizeof(float); // 98816 B
    cudaFuncSetAttribute(fused_fea_kernel, cudaFuncAttributeMaxDynamicSharedMemorySize, (int)smem);
    fused_fea_kernel<<<256, NTHREADS, smem>>>(x, W1, W2, out);
}

// round 10
// speedup vs baseline: 1.2809x; 1.1133x over previous
#include <cuda_runtime.h>

// Warp-specialized pipeline, 384 threads/CTA, 2 CTAs/SM, one CTA per batch.
//   tid 0-255  (G, 8 warps): P1 (fc1, 2 channels/thread o-packed) + P3 (fc2).
//   tid 256-351(S, 3 warps): 96 sequential material chains, 4-t batched LDS/STS.
//   tid 352-383:             stages x tiles global->shared (transposed [f][t]).
// buf layout [l][TPAD] (time contiguous). Slot k: G does P3(k-1), G-barrier,
// P1(k+1); S does P2(k) + stage(k+2) concurrently; one __syncthreads per slot.

typedef unsigned long long u64;

#define NTHREADS 384
#define TT 32
#define NTILES 32
#define TPAD 36
#define XPAD 36
#define WPAD 20
#define XSZ  (16 * XPAD)
#define BSZ  (256 * TPAD)

__device__ __forceinline__ u64 ffma2(u64 a, u64 b, u64 c) {
    u64 d; asm("fma.rn.f32x2 %0, %1, %2, %3;" : "=l"(d) : "l"(a), "l"(b), "l"(c)); return d;
}
__device__ __forceinline__ u64 addf2(u64 a, u64 b) {
    u64 d; asm("add.rn.f32x2 %0, %1, %2;" : "=l"(d) : "l"(a), "l"(b)); return d;
}
__device__ __forceinline__ u64 pack2(float a, float b) {
    u64 r; asm("mov.b64 %0, {%1, %2};" : "=l"(r) : "f"(a), "f"(b)); return r;
}
__device__ __forceinline__ u64 dup2(float a) {
    u64 r; asm("mov.b64 %0, {%1, %1};" : "=l"(r) : "f"(a)); return r;
}
__device__ __forceinline__ float2 unpack2(u64 v) {
    float2 r; asm("mov.b64 {%0, %1}, %2;" : "=f"(r.x), "=f"(r.y) : "l"(v)); return r;
}

// ---- material constants (reference float32 values) ----
#define NUv    0.3f
#define CEL00  (200.0f / 0.91f)
#define CEL01  (CEL00 * 0.3f)
#define CEL22  (CEL00 * 0.35f)
#define INV_E  (1.0f / 200.0f)
#define INV_G  (2.6f / 200.0f)
#define GMODc  (200.0f / 2.6f)
#define SY0c   2.0f
#define HARDc  10.0f
#define INV3GH (1.0f / (3.0f * GMODc + HARDc))
#define KPEN   50.0f
#define D0c    0.1f
#define INV_DFm (1.0f / 0.9f)

__device__ __forceinline__ void j2_step(float& e1, float& e2, float& e12,
                                        float& ep1, float& ep2, float& ep12, float& epbar)
{
    float d1 = e1 - ep1, d2 = e2 - ep2, d12 = e12 - ep12;
    float s1  = CEL00 * d1 + CEL01 * d2;
    float s2  = CEL01 * d1 + CEL00 * d2;
    float s12 = CEL22 * d12;
    float qv  = fmaxf(s1 * s1 - s1 * s2 + s2 * s2 + 3.0f * s12 * s12, 1e-12f);
    float rs  = rsqrtf(qv);
    float seq = qv * rs;
    float fy  = seq - (SY0c + HARDc * epbar);
    bool  pl  = fy > 0.0f;
    epbar += fmaxf(fy, 0.0f) * INV3GH;
    float r = pl ? (SY0c + HARDc * epbar) * rs : 1.0f;
    s1 *= r; s2 *= r; s12 *= r;
    ep1  = pl ? e1  - (s1 - NUv * s2) * INV_E : ep1;
    ep2  = pl ? e2  - (s2 - NUv * s1) * INV_E : ep2;
    ep12 = pl ? e12 - s12 * INV_G             : ep12;
    e1 = s1; e2 = s2; e12 = s12;
}

__device__ __forceinline__ void coh_step(float& dn, float& ds, float& hist)
{
    float dnp = fmaxf(dn, 0.0f);
    float q2  = fmaxf(dnp * dnp + ds * ds, 1e-12f);
    float lam = q2 * rsqrtf(q2);
    hist = fmaxf(hist, lam);
    float dmg = __fdividef(hist - D0c, hist) * INV_DFm;
    dmg = fminf(fmaxf(dmg, 0.0f), 1.0f);
    float omd = 1.0f - dmg;
    float tn = KPEN * dn * (dn > 0.0f ? omd : 1.0f);
    ds = omd * KPEN * ds;
    dn = tn;
}

// channel -> buf row (cohesive channels stored comp-planar)
__device__ __forceinline__ int row_of(int c) {
    return (c < 192) ? c : 192 + ((c - 192) >> 1) + 32 * (c & 1);
}

__global__ void __launch_bounds__(NTHREADS, 2)
fused_fea_kernel(const float* __restrict__ x, const float* __restrict__ W1,
                 const float* __restrict__ W2, float* __restrict__ out)
{
    extern __shared__ float sm[];
    float* SW2s = sm;                    // 256*WPAD, softplus(W2) [l][o]
    float* xsd  = sm + 256 * WPAD;       // 2 * XSZ, x transposed [f][t]
    float* buf  = xsd + 2 * XSZ;         // 2 * BSZ, [l][t]

    const int tid = threadIdx.x;
    const int b   = blockIdx.x;
    const bool isG = (tid < 256);

    const float* xb = x   + (size_t)b * (1024 * 16);
    float*       ob = out + (size_t)b * (1024 * 16);

    // ---- Prologue ----
    for (int i = tid; i < 4096; i += NTHREADS) {
        int o = i >> 8, l = i & 255;
        SW2s[l * WPAD + o] = log1pf(expf(W2[i]));
    }
    if (tid >= 352) {
        const int j = tid - 352;
#pragma unroll
        for (int tile = 0; tile < 2; ++tile) {
            const float4* src = (const float4*)(xb + tile * (TT * 16) + j * 16);
            float* dst = xsd + tile * XSZ + j;
            float4 v0 = src[0], v1 = src[1], v2 = src[2], v3 = src[3];
            dst[0*XPAD] = v0.x; dst[1*XPAD]  = v0.y; dst[2*XPAD]  = v0.z; dst[3*XPAD]  = v0.w;
            dst[4*XPAD] = v1.x; dst[5*XPAD]  = v1.y; dst[6*XPAD]  = v1.z; dst[7*XPAD]  = v1.w;
            dst[8*XPAD] = v2.x; dst[9*XPAD]  = v2.y; dst[10*XPAD] = v2.z; dst[11*XPAD] = v2.w;
            dst[12*XPAD]= v3.x; dst[13*XPAD] = v3.y; dst[14*XPAD] = v3.z; dst[15*XPAD] = v3.w;
        }
    }

    // G/P1 setup: packed channel pair (c, c+128), c = tid&127; warp t-half th.
    u64 wreg[16];
    int row0 = 0, row1 = 0, th = 0;
    if (isG) {
        const int c = tid & 127;
        th = tid >> 7;                   // 0: t 0..15, 1: t 16..31
        row0 = row_of(c);
        row1 = row_of(c + 128);
#pragma unroll
        for (int f = 0; f < 16; ++f)
            wreg[f] = pack2(W1[c * 16 + f], W1[(c + 128) * 16 + f]);
    }

    // S chain state
    float ep1 = 0.f, ep2 = 0.f, ep12 = 0.f, epbar = 0.f, hist = 0.f;
    const int s = tid - 256;

    // P3 coords: lc = l-strip (l = 8i+lc), oq = output quad, tb = 4-t group.
    const int lc = tid & 7;
    const int oq = (tid >> 3) & 3;
    const int tb = tid >> 5;
    const int rowc_base = 192 + (lc >> 1) + 32 * (lc & 1);

    __syncthreads();

    // ===== P1: channel pair o-packed, warp covers 16 t (4 groups of 4) =====
#define P1_TILE(BSEL, XSEL)                                                   \
    {                                                                         \
        float* bufb = buf + (BSEL) * BSZ;                                     \
        const float* xsb = xsd + (XSEL) * XSZ + 16 * th;                      \
        _Pragma("unroll")                                                     \
        for (int g = 0; g < 4; ++g) {                                         \
            const int t = g * 4;                                              \
            u64 a0 = 0, a1 = 0, a2 = 0, a3 = 0;                               \
            _Pragma("unroll")                                                 \
            for (int f = 0; f < 16; ++f) {                                    \
                float4 xq = *(const float4*)(xsb + f * XPAD + t);             \
                a0 = ffma2(wreg[f], dup2(xq.x), a0);                          \
                a1 = ffma2(wreg[f], dup2(xq.y), a1);                          \
                a2 = ffma2(wreg[f], dup2(xq.z), a2);                          \
                a3 = ffma2(wreg[f], dup2(xq.w), a3);                          \
            }                                                                 \
            float2 h0 = unpack2(a0), h1 = unpack2(a1);                        \
            float2 h2 = unpack2(a2), h3 = unpack2(a3);                        \
            float4 v0; v0.x = h0.x; v0.y = h1.x; v0.z = h2.x; v0.w = h3.x;    \
            float4 v1; v1.x = h0.y; v1.y = h1.y; v1.z = h2.y; v1.w = h3.y;    \
            *(float4*)(bufb + row0 * TPAD + 16 * th + t) = v0;                \
            *(float4*)(bufb + row1 * TPAD + 16 * th + t) = v1;                \
        }                                                                     \
    }

    // ===== P3 (R7 structure — known-best MIO shape) =====
#define P3_TILE(BSEL, TOUT)                                                   \
    {                                                                         \
        const float* bufb = buf + (BSEL) * BSZ;                               \
        u64 acc[8];                                                           \
        _Pragma("unroll")                                                     \
        for (int m = 0; m < 8; ++m) acc[m] = 0ull;                            \
        const float* ybulk = bufb + lc * TPAD + 4 * tb;                       \
        const float* wrow  = SW2s + lc * WPAD + 4 * oq;                       \
        _Pragma("unroll 4")                                                   \
        for (int i = 0; i < 24; ++i) {                                        \
            ulonglong2 yv = *(const ulonglong2*)(ybulk + i * 8 * TPAD);       \
            ulonglong2 wv = *(const ulonglong2*)(wrow + i * 8 * WPAD);        \
            float2 y01 = unpack2(yv.x), y23 = unpack2(yv.y);                  \
            u64 y0 = dup2(y01.x), y1 = dup2(y01.y);                           \
            u64 y2 = dup2(y23.x), y3 = dup2(y23.y);                           \
            acc[0] = ffma2(wv.x, y0, acc[0]); acc[1] = ffma2(wv.y, y0, acc[1]); \
            acc[2] = ffma2(wv.x, y1, acc[2]); acc[3] = ffma2(wv.y, y1, acc[3]); \
            acc[4] = ffma2(wv.x, y2, acc[4]); acc[5] = ffma2(wv.y, y2, acc[5]); \
            acc[6] = ffma2(wv.x, y3, acc[6]); acc[7] = ffma2(wv.y, y3, acc[7]); \
        }                                                                     \
        const float* ycoh = bufb + rowc_base * TPAD + 4 * tb;                 \
        _Pragma("unroll 4")                                                   \
        for (int i = 24; i < 32; ++i) {                                       \
            ulonglong2 yv = *(const ulonglong2*)(ycoh + (i - 24) * 4 * TPAD); \
            ulonglong2 wv = *(const ulonglong2*)(wrow + i * 8 * WPAD);        \
            float2 y01 = unpack2(yv.x), y23 = unpack2(yv.y);                  \
            u64 y0 = dup2(y01.x), y1 = dup2(y01.y);                           \
            u64 y2 = dup2(y23.x), y3 = dup2(y23.y);                           \
            acc[0] = ffma2(wv.x, y0, acc[0]); acc[1] = ffma2(wv.y, y0, acc[1]); \
            acc[2] = ffma2(wv.x, y1, acc[2]); acc[3] = ffma2(wv.y, y1, acc[3]); \
            acc[4] = ffma2(wv.x, y2, acc[4]); acc[5] = ffma2(wv.y, y2, acc[5]); \
            acc[6] = ffma2(wv.x, y3, acc[6]); acc[7] = ffma2(wv.y, y3, acc[7]); \
        }                                                                     \
        _Pragma("unroll")                                                     \
        for (int m = 0; m < 8; ++m) {                                         \
            acc[m] = addf2(acc[m], __shfl_xor_sync(0xffffffffu, acc[m], 1));  \
            acc[m] = addf2(acc[m], __shfl_xor_sync(0xffffffffu, acc[m], 2));  \
            acc[m] = addf2(acc[m], __shfl_xor_sync(0xffffffffu, acc[m], 4));  \
        }                                                                     \
        if (lc == 0) {                                                        \
            float* og = ob + (size_t)((TOUT) + 4 * tb) * 16 + 4 * oq;         \
            _Pragma("unroll")                                                 \
            for (int j = 0; j < 4; ++j) {                                     \
                float2 p0 = unpack2(acc[2 * j]);                              \
                float2 p1 = unpack2(acc[2 * j + 1]);                          \
                float4 v; v.x = p0.x; v.y = p0.y; v.z = p1.x; v.w = p1.y;     \
                *(float4*)(og + j * 16) = v;                                  \
            }                                                                 \
        }                                                                     \
    }

    // ---- Fill: P1(0) ----
    if (isG) P1_TILE(0, 0);
    __syncthreads();

    // ---- Pipelined slots ----
    for (int k = 0; k < NTILES; ++k) {
        if (isG) {
            if (k >= 1) P3_TILE((k - 1) & 1, (k - 1) * TT);
            // G-only barrier: P3 reads complete before P1(k+1) overwrites buffer.
            asm volatile("bar.sync 1, 256;" ::: "memory");
            if (k + 1 < NTILES) P1_TILE((k + 1) & 1, (k + 1) & 1);
        } else if (s < 64) {
            // J2 bulk: rows 3s..3s+2; 4 timesteps per LDS/STS.128.
            float* r0 = buf + (k & 1) * BSZ + (3 * s) * TPAD;
#pragma unroll
            for (int g = 0; g < 8; ++g) {
                float4 E1 = *(float4*)(r0 + 4 * g);
                float4 E2 = *(float4*)(r0 + TPAD + 4 * g);
                float4 E3 = *(float4*)(r0 + 2 * TPAD + 4 * g);
                j2_step(E1.x, E2.x, E3.x, ep1, ep2, ep12, epbar);
                j2_step(E1.y, E2.y, E3.y, ep1, ep2, ep12, epbar);
                j2_step(E1.z, E2.z, E3.z, ep1, ep2, ep12, epbar);
                j2_step(E1.w, E2.w, E3.w, ep1, ep2, ep12, epbar);
                *(float4*)(r0 + 4 * g) = E1;
                *(float4*)(r0 + TPAD + 4 * g) = E2;
                *(float4*)(r0 + 2 * TPAD + 4 * g) = E3;
            }
        } else if (s < 96) {
            // Cohesive: dn row 192+j, ds row 224+j.
            const int j = s - 64;
            float* rdn = buf + (k & 1) * BSZ + (192 + j) * TPAD;
            float* rds = buf + (k & 1) * BSZ + (224 + j) * TPAD;
#pragma unroll
            for (int g = 0; g < 8; ++g) {
                float4 DN = *(float4*)(rdn + 4 * g);
                float4 DS = *(float4*)(rds + 4 * g);
                coh_step(DN.x, DS.x, hist);
                coh_step(DN.y, DS.y, hist);
                coh_step(DN.z, DS.z, hist);
                coh_step(DN.w, DS.w, hist);
                *(float4*)(rdn + 4 * g) = DN;
                *(float4*)(rds + 4 * g) = DS;
            }
        } else {
            // Stager: x tile (k+2) -> xsd[k&1], transposed [f][t].
            if (k + 2 < NTILES) {
                const int j = tid - 352;
                const float4* src = (const float4*)(xb + (k + 2) * (TT * 16) + j * 16);
                float* dst = xsd + (k & 1) * XSZ + j;
                float4 v0 = src[0], v1 = src[1], v2 = src[2], v3 = src[3];
                dst[0*XPAD] = v0.x; dst[1*XPAD]  = v0.y; dst[2*XPAD]  = v0.z; dst[3*XPAD]  = v0.w;
                dst[4*XPAD] = v1.x; dst[5*XPAD]  = v1.y; dst[6*XPAD]  = v1.z; dst[7*XPAD]  = v1.w;
                dst[8*XPAD] = v2.x; dst[9*XPAD]  = v2.y; dst[10*XPAD] = v2.z; dst[11*XPAD] = v2.w;
                dst[12*XPAD]= v3.x; dst[13*XPAD] = v3.y; dst[14*XPAD] = v3.z; dst[15*XPAD] = v3.w;
            }
        }
        __syncthreads();
    }

    // ---- Drain: P3(NTILES-1) ----
    if (isG) P3_TILE((NTILES - 1) & 1, (NTILES - 1) * TT);
}

extern "C" void kernel_launch(void* const* d_in, const int* in_sizes, int n_in,
                              void* d_out, int out_size)
{
    const float* x  = (const float*)d_in[0];
    const float* W1 = (const float*)d_in[1];
    const float* W2 = (const float*)d_in[2];
    float* out = (float*)d_out;

    const size_t smem = (size_t)(256 * WPAD + 2 * XSZ + 2 * BSZ) * sizeof(float); // 98816 B
    cudaFuncSetAttribute(fused_fea_kernel, cudaFuncAttributeMaxDynamicSharedMemorySize, (int)smem);
    fused_fea_kernel<<<256, NTHREADS, smem>>>(x, W1, W2, out);
}